// round 1
// baseline (speedup 1.0000x reference)
#include <cuda_runtime.h>
#include <cuda_bf16.h>

#define Bb 8
#define Nn 4096
#define NC 13
#define BN (Bb*Nn)
#define CCH 2048   // candidate chunk (float4) -> 32KB smem
#define QPB 512    // queries per block (256 threads x 2)

__device__ float4 g_a[BN];            // point_rec packed (x,y,z,|p|^2)
__device__ float4 g_b[BN];            // point packed
__device__ float  g_seg_partial[128];
__device__ float  g_cham_partial[128];
__device__ int    g_is64;

// --- detect whether seg_label buffer is int64 or int32 ---------------------
// Labels are in [0,13). If int64 (little-endian), every odd 32-bit word is 0.
// If int32, odd words are labels of odd-index points (virtually surely some
// nonzero among 256 samples). Reads stay within 512 words (< 32768), valid
// for both widths.
__global__ void detect_kernel(const int* __restrict__ lab) {
    __shared__ int s_any;
    if (threadIdx.x == 0) s_any = 0;
    __syncthreads();
    if (lab[threadIdx.x * 2 + 1] != 0) atomicOr(&s_any, 1);
    __syncthreads();
    if (threadIdx.x == 0) g_is64 = (s_any == 0) ? 1 : 0;
}

// --- pack points into float4 with precomputed squared norm -----------------
__global__ void pack_kernel(const float* __restrict__ rec,
                            const float* __restrict__ pt) {
    int idx = blockIdx.x * 256 + threadIdx.x;
    if (idx < BN) {
        float x = rec[idx * 3 + 0], y = rec[idx * 3 + 1], z = rec[idx * 3 + 2];
        g_a[idx] = make_float4(x, y, z, fmaf(x, x, fmaf(y, y, z * z)));
        x = pt[idx * 3 + 0]; y = pt[idx * 3 + 1]; z = pt[idx * 3 + 2];
        g_b[idx] = make_float4(x, y, z, fmaf(x, x, fmaf(y, y, z * z)));
    }
}

// --- NLL gather + per-block sum ---------------------------------------------
__global__ void seg_kernel(const float* __restrict__ prob,
                           const void* __restrict__ lab) {
    __shared__ float sm[256];
    int idx = blockIdx.x * 256 + threadIdx.x;
    int label;
    if (g_is64) label = (int)((const long long*)lab)[idx];
    else        label = ((const int*)lab)[idx];
    sm[threadIdx.x] = prob[idx * NC + label];
    __syncthreads();
    #pragma unroll
    for (int s = 128; s > 0; s >>= 1) {
        if (threadIdx.x < s) sm[threadIdx.x] += sm[threadIdx.x + s];
        __syncthreads();
    }
    if (threadIdx.x == 0) g_seg_partial[blockIdx.x] = sm[0];
}

// --- chamfer min-distance, one direction per blockIdx.z --------------------
__global__ void __launch_bounds__(256, 1) chamfer_kernel() {
    __shared__ float4 sc[CCH];
    __shared__ float  sred[256];

    const int b   = blockIdx.y;
    const int dir = blockIdx.z;
    const float4* __restrict__ Q  = dir ? g_b : g_a;
    const float4* __restrict__ Cd = dir ? g_a : g_b;

    const int tid   = threadIdx.x;
    const int qbase = b * Nn + blockIdx.x * QPB;

    float4 q0 = Q[qbase + tid];
    float4 q1 = Q[qbase + 256 + tid];
    float m0 = 3.4e38f, m1 = 3.4e38f;

    for (int ch = 0; ch < Nn; ch += CCH) {
        const float4* __restrict__ cp = &Cd[b * Nn + ch];
        #pragma unroll
        for (int k = 0; k < CCH / 256; k++)
            sc[tid + k * 256] = cp[tid + k * 256];
        __syncthreads();

        #pragma unroll 8
        for (int j = 0; j < CCH; j++) {
            float4 c = sc[j];
            float s0   = q0.w + c.w;
            float dot0 = fmaf(q0.x, c.x, fmaf(q0.y, c.y, q0.z * c.z));
            float d0   = fmaf(-2.0f, dot0, s0);
            m0 = fminf(m0, d0);
            float s1   = q1.w + c.w;
            float dot1 = fmaf(q1.x, c.x, fmaf(q1.y, c.y, q1.z * c.z));
            float d1   = fmaf(-2.0f, dot1, s1);
            m1 = fminf(m1, d1);
        }
        __syncthreads();
    }

    sred[tid] = m0 + m1;
    __syncthreads();
    #pragma unroll
    for (int s = 128; s > 0; s >>= 1) {
        if (tid < s) sred[tid] += sred[tid + s];
        __syncthreads();
    }
    if (tid == 0)
        g_cham_partial[dir * 64 + b * 8 + blockIdx.x] = sred[0];
}

// --- final combine: out = (-sum_picked + sum_dist1 + sum_dist2) / (B*N) ----
__global__ void final_kernel(float* __restrict__ out) {
    __shared__ float sm[128];
    int t = threadIdx.x;  // 128 threads
    sm[t] = g_cham_partial[t] - g_seg_partial[t];
    __syncthreads();
    #pragma unroll
    for (int s = 64; s > 0; s >>= 1) {
        if (t < s) sm[t] += sm[t + s];
        __syncthreads();
    }
    if (t == 0) out[0] = sm[0] * (1.0f / (float)BN);
}

extern "C" void kernel_launch(void* const* d_in, const int* in_sizes, int n_in,
                              void* d_out, int out_size) {
    const float* seg_prob  = (const float*)d_in[0];
    const void*  seg_label = (const void*)d_in[1];
    const float* point_rec = (const float*)d_in[2];
    const float* point     = (const float*)d_in[3];

    detect_kernel<<<1, 256>>>((const int*)seg_label);
    pack_kernel<<<128, 256>>>(point_rec, point);
    seg_kernel<<<128, 256>>>(seg_prob, seg_label);
    chamfer_kernel<<<dim3(8, 8, 2), 256>>>();
    final_kernel<<<1, 128>>>((float*)d_out);
}

// round 2
// speedup vs baseline: 1.5333x; 1.5333x over previous
#include <cuda_runtime.h>

#define Bb 8
#define Nn 4096
#define NC 13
#define BN (Bb*Nn)        // 32768 points per set
#define QTOT (2*BN)       // 65536 total queries (both directions)
#define TPB 128
#define QPT 4
#define QPB (TPB*QPT)     // 512 queries per block
#define SL 8              // candidate slices
#define SC (Nn/SL)        // 512 candidates per slice

typedef unsigned long long u64;

__device__ float4      g_qa[BN];        // point_rec queries: (-2x,-2y,-2z, |p|^2)
__device__ float4      g_qb[BN];        // point queries
__device__ ulonglong2  g_ca[2*BN];      // point_rec candidates, duplicated f32x2: [{xx,yy},{zz,ww}]
__device__ ulonglong2  g_cb[2*BN];      // point candidates
__device__ float       g_part[SL*QTOT]; // 2MB partial-min scratch
__device__ float       g_seg_partial[128];
__device__ float       g_cham_partial[128];

// ---- f32x2 helpers ---------------------------------------------------------
__device__ __forceinline__ u64 pk(float lo, float hi) {
    u64 r; asm("mov.b64 %0, {%1, %2};" : "=l"(r) : "f"(lo), "f"(hi)); return r;
}
__device__ __forceinline__ u64 fma2(u64 a, u64 b, u64 c) {
    u64 d; asm("fma.rn.f32x2 %0, %1, %2, %3;" : "=l"(d) : "l"(a), "l"(b), "l"(c)); return d;
}
__device__ __forceinline__ void upk(u64 v, float& lo, float& hi) {
    asm("mov.b64 {%0, %1}, %2;" : "=f"(lo), "=f"(hi) : "l"(v));
}

// ---- pack: queries pre-scaled by -2, candidates duplicated ----------------
__global__ void pack_kernel(const float* __restrict__ rec,
                            const float* __restrict__ pt) {
    int i = blockIdx.x * 256 + threadIdx.x;
    if (i >= BN) return;
    {
        float x = rec[i*3+0], y = rec[i*3+1], z = rec[i*3+2];
        float n = fmaf(x, x, fmaf(y, y, z*z));
        g_qa[i] = make_float4(-2.f*x, -2.f*y, -2.f*z, n);
        g_ca[2*i]   = make_ulonglong2(pk(x, x), pk(y, y));
        g_ca[2*i+1] = make_ulonglong2(pk(z, z), pk(n, n));
    }
    {
        float x = pt[i*3+0], y = pt[i*3+1], z = pt[i*3+2];
        float n = fmaf(x, x, fmaf(y, y, z*z));
        g_qb[i] = make_float4(-2.f*x, -2.f*y, -2.f*z, n);
        g_cb[2*i]   = make_ulonglong2(pk(x, x), pk(y, y));
        g_cb[2*i+1] = make_ulonglong2(pk(z, z), pk(n, n));
    }
}

// ---- NLL gather with inline int64/int32 label-width probe ------------------
__global__ void seg_kernel(const float* __restrict__ prob,
                           const void* __restrict__ lab) {
    __shared__ int s_is64;
    __shared__ float sm[256];
    int t = threadIdx.x;
    const int* l32 = (const int*)lab;
    if (t == 0) s_is64 = 1;
    __syncthreads();
    // Labels < 13. If int64, odd 32-bit words are all 0. Probe first 256 labels
    // (words [1,512), in-bounds for either width).
    if (l32[2*t + 1] != 0) s_is64 = 0;
    __syncthreads();
    int idx = blockIdx.x * 256 + t;
    int label = s_is64 ? (int)((const long long*)lab)[idx] : l32[idx];
    sm[t] = prob[idx * NC + label];
    __syncthreads();
    #pragma unroll
    for (int s = 128; s > 0; s >>= 1) {
        if (t < s) sm[t] += sm[t + s];
        __syncthreads();
    }
    if (t == 0) g_seg_partial[blockIdx.x] = sm[0];
}

// ---- chamfer: packed f32x2, 4 queries/thread, sliced candidates -------------
// grid: (64, 8, 2) = (qblk*SL + slice, batch, direction)
__global__ void __launch_bounds__(TPB, 7) chamfer_kernel() {
    __shared__ ulonglong2 scd[SC * 2];   // 16KB: per candidate {xx,yy},{zz,ww}

    const int qblk = blockIdx.x >> 3;
    const int sl   = blockIdx.x & 7;
    const int b    = blockIdx.y;
    const int dir  = blockIdx.z;
    const int t    = threadIdx.x;

    const float4*     __restrict__ Q  = dir ? g_qb : g_qa;
    const ulonglong2* __restrict__ Cd = dir ? g_ca : g_cb;

    // load & pack 4 queries (2 f32x2 chains)
    const int qbase = b * Nn + qblk * QPB;
    float4 q0 = Q[qbase + t],       q1 = Q[qbase + TPB   + t];
    float4 q2 = Q[qbase + 2*TPB + t], q3 = Q[qbase + 3*TPB + t];
    u64 ax = pk(q0.x, q1.x), ay = pk(q0.y, q1.y), az = pk(q0.z, q1.z);
    u64 bx = pk(q2.x, q3.x), by = pk(q2.y, q3.y), bz = pk(q2.z, q3.z);

    // stage this slice's candidates into smem
    const ulonglong2* __restrict__ src = Cd + (size_t)(b * Nn + sl * SC) * 2;
    #pragma unroll
    for (int i = 0; i < 2 * SC / TPB; i++)
        scd[t + i * TPB] = src[t + i * TPB];
    __syncthreads();

    float m0 = 3.4e38f, m1 = 3.4e38f, m2 = 3.4e38f, m3 = 3.4e38f;
    #pragma unroll 4
    for (int j = 0; j < SC; j++) {
        ulonglong2 p0 = scd[2*j];      // {cx,cx},{cy,cy}
        ulonglong2 p1 = scd[2*j + 1];  // {cz,cz},{cn,cn}
        float lo, hi;
        u64 ta = fma2(ax, p0.x, p1.y);
        ta = fma2(ay, p0.y, ta);
        ta = fma2(az, p1.x, ta);
        upk(ta, lo, hi);
        m0 = fminf(m0, lo); m1 = fminf(m1, hi);
        u64 tb = fma2(bx, p0.x, p1.y);
        tb = fma2(by, p0.y, tb);
        tb = fma2(bz, p1.x, tb);
        upk(tb, lo, hi);
        m2 = fminf(m2, lo); m3 = fminf(m3, hi);
    }

    // partial dist = min_c(cn - 2 q.c) ; add query norm now
    const int qg = (dir * Bb + b) * Nn + qblk * QPB;
    float* __restrict__ out = g_part + (size_t)sl * QTOT + qg;
    out[t]         = m0 + q0.w;
    out[t + TPB]   = m1 + q1.w;
    out[t + 2*TPB] = m2 + q2.w;
    out[t + 3*TPB] = m3 + q3.w;
}

// ---- combine: min over slices, sum-reduce ----------------------------------
__global__ void combine_kernel() {
    __shared__ float sm[512];
    int t = threadIdx.x;
    int q = blockIdx.x * 512 + t;
    float m = g_part[q];
    #pragma unroll
    for (int s = 1; s < SL; s++)
        m = fminf(m, g_part[(size_t)s * QTOT + q]);
    sm[t] = m;
    __syncthreads();
    #pragma unroll
    for (int s = 256; s > 0; s >>= 1) {
        if (t < s) sm[t] += sm[t + s];
        __syncthreads();
    }
    if (t == 0) g_cham_partial[blockIdx.x] = sm[0];
}

// ---- final: (sum_cham - sum_picked) / BN ------------------------------------
__global__ void final_kernel(float* __restrict__ out) {
    __shared__ float sm[128];
    int t = threadIdx.x;
    sm[t] = g_cham_partial[t] - g_seg_partial[t];
    __syncthreads();
    #pragma unroll
    for (int s = 64; s > 0; s >>= 1) {
        if (t < s) sm[t] += sm[t + s];
        __syncthreads();
    }
    if (t == 0) out[0] = sm[0] * (1.0f / (float)BN);
}

extern "C" void kernel_launch(void* const* d_in, const int* in_sizes, int n_in,
                              void* d_out, int out_size) {
    const float* seg_prob  = (const float*)d_in[0];
    const void*  seg_label = (const void*)d_in[1];
    const float* point_rec = (const float*)d_in[2];
    const float* point     = (const float*)d_in[3];

    pack_kernel<<<128, 256>>>(point_rec, point);
    seg_kernel<<<128, 256>>>(seg_prob, seg_label);
    chamfer_kernel<<<dim3(64, 8, 2), TPB>>>();
    combine_kernel<<<128, 512>>>();
    final_kernel<<<1, 128>>>((float*)d_out);
}

// round 3
// speedup vs baseline: 1.7989x; 1.1732x over previous
#include <cuda_runtime.h>

#define Bb 8
#define Nn 4096
#define NC 13
#define BN (Bb*Nn)        // 32768 points per set
#define QTOT (2*BN)       // 65536 query mins (both directions)
#define TPB 128
#define QPT 4
#define QPB (TPB*QPT)     // 512 queries per block
#define SL 8              // candidate slices
#define SC (Nn/SL)        // 512 candidates per slice
#define SP (SC/2)         // 256 candidate pairs per slice

typedef unsigned long long u64;

__device__ float4     g_qa[BN];     // point_rec queries: (-2x,-2y,-2z,|p|^2)
__device__ float4     g_qb[BN];     // point queries
__device__ ulonglong2 g_cpa[BN];    // rec candidates, pair-packed: pair p -> [2p]={xx',yy'} [2p+1]={zz',nn'}
__device__ ulonglong2 g_cpb[BN];    // point candidates, pair-packed
__device__ int        g_min[QTOT];  // running min of squared distance (positive -> int order ok)
__device__ float      g_seg_partial[128];
__device__ float      g_cham_partial[64];

// ---- f32x2 helpers ----------------------------------------------------------
__device__ __forceinline__ u64 pk(float lo, float hi) {
    u64 r; asm("mov.b64 %0, {%1, %2};" : "=l"(r) : "f"(lo), "f"(hi)); return r;
}
__device__ __forceinline__ u64 fma2(u64 a, u64 b, u64 c) {
    u64 d; asm("fma.rn.f32x2 %0, %1, %2, %3;" : "=l"(d) : "l"(a), "l"(b), "l"(c)); return d;
}
__device__ __forceinline__ float min2(u64 v, float m) {
    float lo, hi;
    asm("mov.b64 {%0, %1}, %2;" : "=f"(lo), "=f"(hi) : "l"(v));
    return fminf(m, fminf(lo, hi));
}

// ---- fused pack (+g_min init) and NLL gather --------------------------------
// grid 256 x 256: blocks [0,128) pack, blocks [128,256) seg
__global__ void prep_kernel(const float* __restrict__ rec,
                            const float* __restrict__ pt,
                            const float* __restrict__ prob,
                            const void* __restrict__ lab) {
    int t = threadIdx.x;
    if (blockIdx.x < 128) {
        int i = blockIdx.x * 256 + t;
        float x0 = rec[i*3+0], y0 = rec[i*3+1], z0 = rec[i*3+2];
        float na = fmaf(x0, x0, fmaf(y0, y0, z0*z0));
        g_qa[i] = make_float4(-2.f*x0, -2.f*y0, -2.f*z0, na);
        float x1 = pt[i*3+0], y1 = pt[i*3+1], z1 = pt[i*3+2];
        float nb = fmaf(x1, x1, fmaf(y1, y1, z1*z1));
        g_qb[i] = make_float4(-2.f*x1, -2.f*y1, -2.f*z1, nb);
        g_min[i]      = 0x7F800000;   // +inf
        g_min[BN + i] = 0x7F800000;
        if ((i & 1) == 0) {           // pack candidate pair (i, i+1)
            float xa = rec[i*3+3], ya = rec[i*3+4], za = rec[i*3+5];
            float naa = fmaf(xa, xa, fmaf(ya, ya, za*za));
            g_cpa[i]   = make_ulonglong2(pk(x0, xa), pk(y0, ya));
            g_cpa[i+1] = make_ulonglong2(pk(z0, za), pk(na, naa));
            float xb = pt[i*3+3], yb = pt[i*3+4], zb = pt[i*3+5];
            float nbb = fmaf(xb, xb, fmaf(yb, yb, zb*zb));
            g_cpb[i]   = make_ulonglong2(pk(x1, xb), pk(y1, yb));
            g_cpb[i+1] = make_ulonglong2(pk(z1, zb), pk(nb, nbb));
        }
    } else {
        __shared__ int s_is64;
        __shared__ float sm[256];
        const int* l32 = (const int*)lab;
        if (t == 0) s_is64 = 1;
        __syncthreads();
        // Labels < 13; if int64 every odd 32-bit word is 0. Probe 256 labels.
        if (l32[2*t + 1] != 0) s_is64 = 0;
        __syncthreads();
        int idx = (blockIdx.x - 128) * 256 + t;
        int label = s_is64 ? (int)((const long long*)lab)[idx] : l32[idx];
        sm[t] = prob[idx * NC + label];
        __syncthreads();
        #pragma unroll
        for (int s = 128; s > 0; s >>= 1) {
            if (t < s) sm[t] += sm[t + s];
            __syncthreads();
        }
        if (t == 0) g_seg_partial[blockIdx.x - 128] = sm[0];
    }
}

// ---- chamfer: f32x2 over candidate pairs, atomic-min merge ------------------
// grid: (64, 8, 2): x = qblk*8 + slice, y = batch, z = direction
__global__ void __launch_bounds__(TPB, 8) chamfer_kernel() {
    __shared__ ulonglong2 scd[SC];   // 8KB: SP pairs x 2 entries

    const int qblk = blockIdx.x >> 3;
    const int sl   = blockIdx.x & 7;
    const int b    = blockIdx.y;
    const int dir  = blockIdx.z;
    const int t    = threadIdx.x;

    const float4*     __restrict__ Q  = dir ? g_qb : g_qa;
    const ulonglong2* __restrict__ Cp = dir ? g_cpa : g_cpb;

    const int qbase = b * Nn + qblk * QPB;
    float4 q0 = Q[qbase + t],         q1 = Q[qbase + TPB + t];
    float4 q2 = Q[qbase + 2*TPB + t], q3 = Q[qbase + 3*TPB + t];
    // duplicate each query component into both f32x2 lanes (once, outside loop)
    u64 x0 = pk(q0.x,q0.x), y0v = pk(q0.y,q0.y), z0v = pk(q0.z,q0.z);
    u64 x1 = pk(q1.x,q1.x), y1v = pk(q1.y,q1.y), z1v = pk(q1.z,q1.z);
    u64 x2 = pk(q2.x,q2.x), y2v = pk(q2.y,q2.y), z2v = pk(q2.z,q2.z);
    u64 x3 = pk(q3.x,q3.x), y3v = pk(q3.y,q3.y), z3v = pk(q3.z,q3.z);

    const ulonglong2* __restrict__ src = Cp + b * Nn + sl * SC;
    #pragma unroll
    for (int i = 0; i < SC / TPB; i++)
        scd[t + i * TPB] = src[t + i * TPB];
    __syncthreads();

    float m0 = 3.4e38f, m1 = 3.4e38f, m2 = 3.4e38f, m3 = 3.4e38f;
    #pragma unroll 8
    for (int jp = 0; jp < SP; jp++) {
        ulonglong2 p0 = scd[2*jp];      // {cx,cx'},{cy,cy'}
        ulonglong2 p1 = scd[2*jp + 1];  // {cz,cz'},{cn,cn'}
        u64 t0 = fma2(z0v, p1.x, p1.y); t0 = fma2(y0v, p0.y, t0); t0 = fma2(x0, p0.x, t0);
        u64 t1 = fma2(z1v, p1.x, p1.y); t1 = fma2(y1v, p0.y, t1); t1 = fma2(x1, p0.x, t1);
        u64 t2 = fma2(z2v, p1.x, p1.y); t2 = fma2(y2v, p0.y, t2); t2 = fma2(x2, p0.x, t2);
        u64 t3 = fma2(z3v, p1.x, p1.y); t3 = fma2(y3v, p0.y, t3); t3 = fma2(x3, p0.x, t3);
        m0 = min2(t0, m0);
        m1 = min2(t1, m1);
        m2 = min2(t2, m2);
        m3 = min2(t3, m3);
    }

    // add query norm -> true squared distance (>=0), merge across slices
    int* __restrict__ gm = g_min + (dir * Bb + b) * Nn + qblk * QPB;
    atomicMin(gm + t,         __float_as_int(m0 + q0.w));
    atomicMin(gm + t + TPB,   __float_as_int(m1 + q1.w));
    atomicMin(gm + t + 2*TPB, __float_as_int(m2 + q2.w));
    atomicMin(gm + t + 3*TPB, __float_as_int(m3 + q3.w));
}

// ---- combine: sum the 65536 mins ---------------------------------------------
__global__ void combine_kernel() {
    __shared__ float sm[256];
    int t = threadIdx.x;
    int4 v = ((const int4*)g_min)[blockIdx.x * 256 + t];
    sm[t] = __int_as_float(v.x) + __int_as_float(v.y) +
            __int_as_float(v.z) + __int_as_float(v.w);
    __syncthreads();
    #pragma unroll
    for (int s = 128; s > 0; s >>= 1) {
        if (t < s) sm[t] += sm[t + s];
        __syncthreads();
    }
    if (t == 0) g_cham_partial[blockIdx.x] = sm[0];
}

// ---- final: (sum_cham - sum_picked) / BN -------------------------------------
__global__ void final_kernel(float* __restrict__ out) {
    __shared__ float sm[64];
    int t = threadIdx.x;  // 64 threads
    sm[t] = g_cham_partial[t] - g_seg_partial[t] - g_seg_partial[t + 64];
    __syncthreads();
    #pragma unroll
    for (int s = 32; s > 0; s >>= 1) {
        if (t < s) sm[t] += sm[t + s];
        __syncthreads();
    }
    if (t == 0) out[0] = sm[0] * (1.0f / (float)BN);
}

extern "C" void kernel_launch(void* const* d_in, const int* in_sizes, int n_in,
                              void* d_out, int out_size) {
    const float* seg_prob  = (const float*)d_in[0];
    const void*  seg_label = (const void*)d_in[1];
    const float* point_rec = (const float*)d_in[2];
    const float* point     = (const float*)d_in[3];

    prep_kernel<<<256, 256>>>(point_rec, point, seg_prob, seg_label);
    chamfer_kernel<<<dim3(64, 8, 2), TPB>>>();
    combine_kernel<<<64, 256>>>();
    final_kernel<<<1, 64>>>((float*)d_out);
}